// round 1
// baseline (speedup 1.0000x reference)
#include <cuda_runtime.h>
#include <cuda_bf16.h>

#define T_DIM 8192

__global__ void wl_zero(float* out) {
    if (threadIdx.x == 0) out[0] = 0.0f;
}

__global__ void __launch_bounds__(256)
wl_reduce(const float4* __restrict__ a, const float4* __restrict__ b,
          float* __restrict__ out, int n4, float scale) {
    float acc = 0.0f;
    const int stride = gridDim.x * blockDim.x;
    for (int i = blockIdx.x * blockDim.x + threadIdx.x; i < n4; i += stride) {
        float4 va = a[i];
        float4 vb = b[i];
        int t = (i << 2) & (T_DIM - 1);
        float w = (float)(T_DIM - t);
        acc = fmaf(fabsf(va.x - vb.x), w,        acc);
        acc = fmaf(fabsf(va.y - vb.y), w - 1.0f, acc);
        acc = fmaf(fabsf(va.z - vb.z), w - 2.0f, acc);
        acc = fmaf(fabsf(va.w - vb.w), w - 3.0f, acc);
    }
    // intra-warp reduce
    #pragma unroll
    for (int o = 16; o > 0; o >>= 1)
        acc += __shfl_down_sync(0xffffffffu, acc, o);

    __shared__ float smem[8];
    int lane = threadIdx.x & 31;
    int wid  = threadIdx.x >> 5;
    if (lane == 0) smem[wid] = acc;
    __syncthreads();
    if (wid == 0) {
        acc = (lane < 8) ? smem[lane] : 0.0f;
        #pragma unroll
        for (int o = 4; o > 0; o >>= 1)
            acc += __shfl_down_sync(0xffffffffu, acc, o);
        if (lane == 0) atomicAdd(out, acc * scale);
    }
}

extern "C" void kernel_launch(void* const* d_in, const int* in_sizes, int n_in,
                              void* d_out, int out_size) {
    const float4* y_pred = (const float4*)d_in[0];
    const float4* y_true = (const float4*)d_in[1];
    float* out = (float*)d_out;

    const int n = in_sizes[0];          // 32*64*8192 = 16777216
    const int n4 = n / 4;

    // B*C*T = n, T = 8192, C = 64, B = 32
    const double T = (double)T_DIM;
    const double C = 64.0;
    const double B = (double)n / (T * C);
    const float scale = (float)(2.0 / (T * C * (T + 1.0) * B));

    wl_zero<<<1, 32>>>(out);

    const int threads = 256;
    int blocks = 2048;
    int max_blocks = (n4 + threads - 1) / threads;
    if (blocks > max_blocks) blocks = max_blocks;
    wl_reduce<<<blocks, threads>>>(y_pred, y_true, out, n4, scale);
}

// round 2
// speedup vs baseline: 1.0619x; 1.0619x over previous
#include <cuda_runtime.h>
#include <cuda_bf16.h>

#define T_DIM 8192

__device__ float        g_scratch = 0.0f;
__device__ unsigned int g_count   = 0u;

__global__ void __launch_bounds__(256)
wl_reduce(const float4* __restrict__ a, const float4* __restrict__ b,
          float* __restrict__ out, int n4, float scale) {
    const int stride = gridDim.x * blockDim.x;
    int i = blockIdx.x * blockDim.x + threadIdx.x;

    float acc0 = 0.0f, acc1 = 0.0f, acc2 = 0.0f, acc3 = 0.0f;

    // Main unrolled loop: 8 independent LDG.128 in flight per iteration.
    for (; i + 3 * stride < n4; i += 4 * stride) {
        const int i0 = i, i1 = i + stride, i2 = i + 2 * stride, i3 = i + 3 * stride;
        float4 a0 = __ldcs(a + i0);
        float4 a1 = __ldcs(a + i1);
        float4 a2 = __ldcs(a + i2);
        float4 a3 = __ldcs(a + i3);
        float4 b0 = __ldcs(b + i0);
        float4 b1 = __ldcs(b + i1);
        float4 b2 = __ldcs(b + i2);
        float4 b3 = __ldcs(b + i3);

        float w0 = (float)(T_DIM - ((i0 << 2) & (T_DIM - 1)));
        float w1 = (float)(T_DIM - ((i1 << 2) & (T_DIM - 1)));
        float w2 = (float)(T_DIM - ((i2 << 2) & (T_DIM - 1)));
        float w3 = (float)(T_DIM - ((i3 << 2) & (T_DIM - 1)));

        acc0 = fmaf(fabsf(a0.x - b0.x), w0,        acc0);
        acc0 = fmaf(fabsf(a0.y - b0.y), w0 - 1.0f, acc0);
        acc0 = fmaf(fabsf(a0.z - b0.z), w0 - 2.0f, acc0);
        acc0 = fmaf(fabsf(a0.w - b0.w), w0 - 3.0f, acc0);

        acc1 = fmaf(fabsf(a1.x - b1.x), w1,        acc1);
        acc1 = fmaf(fabsf(a1.y - b1.y), w1 - 1.0f, acc1);
        acc1 = fmaf(fabsf(a1.z - b1.z), w1 - 2.0f, acc1);
        acc1 = fmaf(fabsf(a1.w - b1.w), w1 - 3.0f, acc1);

        acc2 = fmaf(fabsf(a2.x - b2.x), w2,        acc2);
        acc2 = fmaf(fabsf(a2.y - b2.y), w2 - 1.0f, acc2);
        acc2 = fmaf(fabsf(a2.z - b2.z), w2 - 2.0f, acc2);
        acc2 = fmaf(fabsf(a2.w - b2.w), w2 - 3.0f, acc2);

        acc3 = fmaf(fabsf(a3.x - b3.x), w3,        acc3);
        acc3 = fmaf(fabsf(a3.y - b3.y), w3 - 1.0f, acc3);
        acc3 = fmaf(fabsf(a3.z - b3.z), w3 - 2.0f, acc3);
        acc3 = fmaf(fabsf(a3.w - b3.w), w3 - 3.0f, acc3);
    }
    // Tail
    for (; i < n4; i += stride) {
        float4 va = __ldcs(a + i);
        float4 vb = __ldcs(b + i);
        float w = (float)(T_DIM - ((i << 2) & (T_DIM - 1)));
        acc0 = fmaf(fabsf(va.x - vb.x), w,        acc0);
        acc0 = fmaf(fabsf(va.y - vb.y), w - 1.0f, acc0);
        acc0 = fmaf(fabsf(va.z - vb.z), w - 2.0f, acc0);
        acc0 = fmaf(fabsf(va.w - vb.w), w - 3.0f, acc0);
    }

    float acc = (acc0 + acc1) + (acc2 + acc3);

    // intra-warp reduce
    #pragma unroll
    for (int o = 16; o > 0; o >>= 1)
        acc += __shfl_down_sync(0xffffffffu, acc, o);

    __shared__ float smem[8];
    const int lane = threadIdx.x & 31;
    const int wid  = threadIdx.x >> 5;
    if (lane == 0) smem[wid] = acc;
    __syncthreads();
    if (wid == 0) {
        acc = (lane < 8) ? smem[lane] : 0.0f;
        #pragma unroll
        for (int o = 4; o > 0; o >>= 1)
            acc += __shfl_down_sync(0xffffffffu, acc, o);

        if (lane == 0) {
            atomicAdd(&g_scratch, acc);
            __threadfence();
            unsigned int old = atomicAdd(&g_count, 1u);
            if (old == gridDim.x - 1) {
                // Last block: publish result, reset scratch for next replay.
                out[0]    = g_scratch * scale;
                g_scratch = 0.0f;
                g_count   = 0u;
            }
        }
    }
}

extern "C" void kernel_launch(void* const* d_in, const int* in_sizes, int n_in,
                              void* d_out, int out_size) {
    const float4* y_pred = (const float4*)d_in[0];
    const float4* y_true = (const float4*)d_in[1];
    float* out = (float*)d_out;

    const int n  = in_sizes[0];   // 32*64*8192
    const int n4 = n / 4;

    const double T = (double)T_DIM;
    const double C = 64.0;
    const double B = (double)n / (T * C);
    const float scale = (float)(2.0 / (T * C * (T + 1.0) * B));

    const int threads = 256;
    int blocks = 2048;
    int max_blocks = (n4 + threads - 1) / threads;
    if (blocks > max_blocks) blocks = max_blocks;

    wl_reduce<<<blocks, threads>>>(y_pred, y_true, out, n4, scale);
}